// round 14
// baseline (speedup 1.0000x reference)
#include <cuda_runtime.h>
#include <cuda_bf16.h>
#include <stdint.h>
#include <math.h>

#define BB 16
#define NN 4096
#define HH 512
#define NHEAD 8
#define MM 512
#define LNEPS 1e-5f

// ---------------- static scratch (no allocations allowed) ----------------
__device__ float g_ppart[BB * 32 * HH];
__device__ float g_gate[BB];
__device__ float g_sal[BB * NN];
__device__ int   g_idx[BB * MM];
__device__ float g_qkv[(size_t)BB * MM * 3 * HH];
__device__ float g_attn[(size_t)BB * MM * HH];
__device__ float g_rel[(size_t)BB * MM * HH];

// ---------------- small kernels ----------------
// persistent grid-stride copy: 64 CTAs only, coexists with the compute chain
__global__ void k_copy(const float4* __restrict__ tok, float4* __restrict__ out) {
    const size_t n = (size_t)BB * NN * HH / 4;
    size_t stride = (size_t)gridDim.x * blockDim.x;
    size_t i = (size_t)blockIdx.x * blockDim.x + threadIdx.x;
#pragma unroll 4
    for (; i < n; i += stride) out[i] = tok[i];
}

// fused pooled-partials + salience, one token pass, warp-per-token reduction.
__global__ void __launch_bounds__(512)
k_poolsal(const float* __restrict__ tok,
          const float* __restrict__ lg, const float* __restrict__ lb,
          const float* __restrict__ w, const float* __restrict__ wb) {
    __shared__ float tile[16][512];
    __shared__ float gw[512];
    __shared__ float red[32];
    __shared__ float sS[2];
    int b = blockIdx.x, c = blockIdx.y;
    int tid = threadIdx.x, lane = tid & 31, wid = tid >> 5;

    float gwv = lg[tid] * w[tid];
    float bwv = lb[tid] * w[tid];
    gw[tid] = gwv;
    {
        float a0 = gwv, a1 = bwv;
#pragma unroll
        for (int o = 16; o; o >>= 1) {
            a0 += __shfl_down_sync(0xffffffffu, a0, o);
            a1 += __shfl_down_sync(0xffffffffu, a1, o);
        }
        if (lane == 0) { red[wid] = a0; red[wid + 16] = a1; }
    }
    __syncthreads();
    if (tid == 0) {
        float s0 = 0.f, s1 = 0.f;
#pragma unroll
        for (int k = 0; k < 16; k++) { s0 += red[k]; s1 += red[k + 16]; }
        sS[0] = s0; sS[1] = s1;
    }
    __syncthreads();
    float Sgw = sS[0], S2 = sS[1];

    const float* p = tok + ((size_t)(b * NN + c * 128)) * HH + tid;
    float pool = 0.f;

    for (int t8 = 0; t8 < 8; t8++) {
#pragma unroll
        for (int r = 0; r < 16; r++) {
            float x = p[(size_t)(t8 * 16 + r) * HH];
            tile[r][tid] = x;
            pool += x;
        }
        __syncthreads();
        {
            float Sx = 0.f, Sxx = 0.f, Sxg = 0.f;
#pragma unroll
            for (int i = 0; i < 16; i++) {
                float x = tile[wid][lane + 32 * i];
                Sx += x; Sxx += x * x; Sxg += x * gw[lane + 32 * i];
            }
#pragma unroll
            for (int o = 16; o; o >>= 1) {
                Sx  += __shfl_down_sync(0xffffffffu, Sx, o);
                Sxx += __shfl_down_sync(0xffffffffu, Sxx, o);
                Sxg += __shfl_down_sync(0xffffffffu, Sxg, o);
            }
            if (lane == 0) {
                float mean = Sx * (1.f / HH);
                float var = Sxx * (1.f / HH) - mean * mean;
                float rstd = rsqrtf(var + LNEPS);
                g_sal[b * NN + c * 128 + t8 * 16 + wid] =
                    rstd * (Sxg - mean * Sgw) + S2 + wb[0];
            }
        }
        __syncthreads();
    }
    g_ppart[(b * 32 + c) * HH + tid] = pool;
}

// merged pool2 + gate: one block per batch, 512 threads
__global__ void __launch_bounds__(512)
k_pool2gate(const float* __restrict__ lg, const float* __restrict__ lb,
            const float* __restrict__ w, const float* __restrict__ wb) {
    __shared__ float red[16];
    int b = blockIdx.x, tid = threadIdx.x, lane = tid & 31, wid = tid >> 5;
    float s = 0.f;
#pragma unroll
    for (int c = 0; c < 32; c++) s += g_ppart[(b * 32 + c) * HH + tid];
    float v = s * (1.f / NN);      // pooled[b][tid]

    // block reduce sum / sumsq over 512 threads
    float a0 = v, a1 = v * v;
#pragma unroll
    for (int o = 16; o; o >>= 1) {
        a0 += __shfl_down_sync(0xffffffffu, a0, o);
        a1 += __shfl_down_sync(0xffffffffu, a1, o);
    }
    if (lane == 0) red[wid] = a0;
    __syncthreads();
    float Sx = 0.f;
    if (tid == 0) {
#pragma unroll
        for (int k = 0; k < 16; k++) Sx += red[k];
        red[0] = Sx;
    }
    __syncthreads();
    Sx = red[0];
    __syncthreads();
    if (lane == 0) red[wid] = a1;
    __syncthreads();
    float Sxx = 0.f;
    if (tid == 0) {
#pragma unroll
        for (int k = 0; k < 16; k++) Sxx += red[k];
        red[0] = Sxx;
    }
    __syncthreads();
    Sxx = red[0];
    __syncthreads();

    float mean = Sx * (1.f / HH);
    float var = Sxx * (1.f / HH) - mean * mean;
    float rstd = rsqrtf(var + LNEPS);
    float d = ((v - mean) * rstd * lg[tid] + lb[tid]) * w[tid];
#pragma unroll
    for (int o = 16; o; o >>= 1) d += __shfl_down_sync(0xffffffffu, d, o);
    if (lane == 0) red[wid] = d;
    __syncthreads();
    if (tid == 0) {
        float dd = 0.f;
#pragma unroll
        for (int k = 0; k < 16; k++) dd += red[k];
        g_gate[b] = 1.f / (1.f + expf(-(dd + wb[0])));
    }
}

// atomic-free topk: slot = rank (all higher-salience tokens are also selected)
__global__ void k_topk() {
    __shared__ float sh[NN];
    int b = blockIdx.x;
    for (int j = threadIdx.x; j < NN; j += 256) sh[j] = g_sal[b * NN + j];
    __syncthreads();
    int i = blockIdx.y * 256 + threadIdx.x;
    float si = sh[i];
    int cnt = 0;
    for (int j = 0; j < NN; j++) {
        float sj = sh[j];
        cnt += (sj > si) || (sj == si && j < i);
    }
    if (cnt < MM) g_idx[b * MM + cnt] = i;
}

// ---------------- BF16 mma / ldmatrix helpers ----------------
__device__ __forceinline__ uint32_t pack_bf(float lo, float hi) {
    __nv_bfloat162 h = __floats2bfloat162_rn(lo, hi);
    return *reinterpret_cast<uint32_t*>(&h);
}

__device__ __forceinline__ void mma16(float* d, const uint32_t* a, const uint32_t* b) {
    asm volatile(
        "mma.sync.aligned.m16n8k16.row.col.f32.bf16.bf16.f32 "
        "{%0,%1,%2,%3}, {%4,%5,%6,%7}, {%8,%9}, {%0,%1,%2,%3};"
        : "+f"(d[0]), "+f"(d[1]), "+f"(d[2]), "+f"(d[3])
        : "r"(a[0]), "r"(a[1]), "r"(a[2]), "r"(a[3]), "r"(b[0]), "r"(b[1]));
}

__device__ __forceinline__ void ldsm4(uint32_t* r, uint32_t saddr) {
    asm volatile(
        "ldmatrix.sync.aligned.m8n8.x4.shared.b16 {%0,%1,%2,%3}, [%4];"
        : "=r"(r[0]), "=r"(r[1]), "=r"(r[2]), "=r"(r[3]) : "r"(saddr));
}

// ---------------- BF16 tensor-core GEMM (double-buffered, ldmatrix) ----------------
template <int MT, int NT, int BWM, int BWN, int GATHER>
__global__ void __launch_bounds__(256, 2)
k_gemm_bf(const float* __restrict__ A, const float* __restrict__ B,
          const float* __restrict__ bias, float* __restrict__ C,
          int K, int lda, int ldb, int ldc, float scale) {
    constexpr int WM = MT / BWM, WN = NT / BWN;
    constexpr int AM = WM / 16, BN = WN / 8;
    constexpr int NA = MT / 32, NB = NT / 32;
    __shared__ uint32_t As[2][MT][20];
    __shared__ uint32_t Bs[2][NT][20];

    int m0 = blockIdx.y * MT, n0 = blockIdx.x * NT;
    int tid = threadIdx.x, lane = tid & 31, wid = tid >> 5;
    int wm = (wid / BWN) * WM, wn = (wid % BWN) * WN;

    float acc[AM][BN][4];
#pragma unroll
    for (int i = 0; i < AM; i++)
#pragma unroll
        for (int j = 0; j < BN; j++) {
            acc[i][j][0] = 0.f; acc[i][j][1] = 0.f;
            acc[i][j][2] = 0.f; acc[i][j][3] = 0.f;
        }

    int lr = tid >> 3;
    int lk = (tid & 7) << 2;
    int lc = (tid & 7) << 1;

    int mi = lane >> 3;
    int rA = (lane & 7) + ((mi & 1) << 3);
    int cA = (mi >> 1) << 2;
    int rB = (lane & 7) + ((mi >> 1) << 3);
    int cB = (mi & 1) << 2;

    const float* arow[NA];
#pragma unroll
    for (int i = 0; i < NA; i++) {
        int r = m0 + lr + 32 * i;
        if (GATHER)
            arow[i] = A + ((size_t)(r >> 9) * NN + g_idx[r]) * HH;
        else
            arow[i] = A + (size_t)r * lda;
    }

    float4 ar[NA], br[NB];

    auto loadT = [&](int k0) {
#pragma unroll
        for (int i = 0; i < NA; i++)
            ar[i] = *(const float4*)(arow[i] + k0 + lk);
#pragma unroll
        for (int i = 0; i < NB; i++)
            br[i] = *(const float4*)(B + (long)(n0 + lr + 32 * i) * ldb + k0 + lk);
    };
    auto storeT = [&](int buf) {
#pragma unroll
        for (int i = 0; i < NA; i++) {
            As[buf][lr + 32 * i][lc]     = pack_bf(ar[i].x, ar[i].y);
            As[buf][lr + 32 * i][lc + 1] = pack_bf(ar[i].z, ar[i].w);
        }
#pragma unroll
        for (int i = 0; i < NB; i++) {
            Bs[buf][lr + 32 * i][lc]     = pack_bf(br[i].x, br[i].y);
            Bs[buf][lr + 32 * i][lc + 1] = pack_bf(br[i].z, br[i].w);
        }
    };

    int nk = K >> 5;
    loadT(0);
    storeT(0);
    __syncthreads();

    for (int kt = 0; kt < nk; kt++) {
        int buf = kt & 1;
        if (kt + 1 < nk) loadT((kt + 1) << 5);
        uint32_t a_base = (uint32_t)__cvta_generic_to_shared(&As[buf][0][0]);
        uint32_t b_base = (uint32_t)__cvta_generic_to_shared(&Bs[buf][0][0]);
#pragma unroll
        for (int ks = 0; ks < 2; ks++) {
            int kc = ks * 8;
            uint32_t af[AM][4];
#pragma unroll
            for (int i = 0; i < AM; i++)
                ldsm4(af[i], a_base + (((wm + i * 16 + rA) * 20 + kc + cA) << 2));
            uint32_t bfr[BN][2];
#pragma unroll
            for (int jp = 0; jp < BN / 2; jp++) {
                uint32_t t4[4];
                ldsm4(t4, b_base + (((wn + jp * 16 + rB) * 20 + kc + cB) << 2));
                bfr[2 * jp][0] = t4[0]; bfr[2 * jp][1] = t4[1];
                bfr[2 * jp + 1][0] = t4[2]; bfr[2 * jp + 1][1] = t4[3];
            }
#pragma unroll
            for (int i = 0; i < AM; i++)
#pragma unroll
                for (int j = 0; j < BN; j++)
                    mma16(acc[i][j], af[i], bfr[j]);
        }
        if (kt + 1 < nk) storeT(buf ^ 1);
        __syncthreads();
    }

#pragma unroll
    for (int i = 0; i < AM; i++) {
        int r0 = m0 + wm + i * 16 + (lane >> 2);
#pragma unroll
        for (int j = 0; j < BN; j++) {
            int c0 = n0 + wn + j * 8 + ((lane & 3) << 1);
            float b0 = 0.f, b1 = 0.f;
            if (bias) { b0 = bias[c0]; b1 = bias[c0 + 1]; }
            float2 o0, o1;
            o0.x = acc[i][j][0] * scale + b0;
            o0.y = acc[i][j][1] * scale + b1;
            o1.x = acc[i][j][2] * scale + b0;
            o1.y = acc[i][j][3] * scale + b1;
            *(float2*)(C + (long)r0 * ldc + c0) = o0;
            *(float2*)(C + (long)(r0 + 8) * ldc + c0) = o1;
        }
    }
}

// ---------------- flash attention (ldmatrix fragments) ----------------
__global__ void __launch_bounds__(256, 2)
k_attn(const float* __restrict__ qkv, float* __restrict__ attn) {
    __shared__ uint32_t Ks[2][64][36];
    __shared__ uint32_t Vs[2][64][36];

    int z = blockIdx.x;
    int qt = z & 3, bh = z >> 2;
    int b = bh >> 3, h = bh & 7;
    int tid = threadIdx.x, lane = tid & 31, wid = tid >> 5;

    const float* base = qkv + (size_t)b * MM * 1536;
    const float* Qg = base + (size_t)(qt * 128) * 1536 + h * 64;
    const float* Kg = base + 512 + h * 64;
    const float* Vg = base + 1024 + h * 64;

    uint32_t* Ksf = &Ks[0][0][0];

    int mi = lane >> 3;
    int rA = (lane & 7) + ((mi & 1) << 3);
    int cA = (mi >> 1) << 2;
    int rB = (lane & 7) + ((mi >> 1) << 3);
    int cB = (mi & 1) << 2;

    {
        int r = tid >> 1, ch = (tid & 1) * 32;
        const float* qp = Qg + (size_t)r * 1536 + ch;
        int o = r * 36 + ch / 2;
#pragma unroll
        for (int i = 0; i < 8; i++) {
            float4 v = *(const float4*)(qp + i * 4);
            Ksf[o + i * 2]     = pack_bf(v.x, v.y);
            Ksf[o + i * 2 + 1] = pack_bf(v.z, v.w);
        }
    }
    __syncthreads();

    int wm = wid * 16;
    uint32_t aq[4][4];
    {
        uint32_t q_base = (uint32_t)__cvta_generic_to_shared(Ksf);
#pragma unroll
        for (int ks = 0; ks < 4; ks++)
            ldsm4(aq[ks], q_base + (((wm + rA) * 36 + ks * 8 + cA) << 2));
    }
    __syncthreads();

    int krow = tid >> 2, kq = tid & 3;
    int vdp = tid & 31, vpg = tid >> 5;
    uint32_t kreg[8], vreg[8];

    auto ldK = [&](int kt) {
        const float* kp = Kg + (size_t)(kt * 64 + krow) * 1536 + kq * 16;
#pragma unroll
        for (int i = 0; i < 4; i++) {
            float4 v = *(const float4*)(kp + i * 4);
            kreg[i * 2]     = pack_bf(v.x, v.y);
            kreg[i * 2 + 1] = pack_bf(v.z, v.w);
        }
    };
    auto stK = [&](int buf) {
#pragma unroll
        for (int i = 0; i < 8; i++) Ks[buf][krow][kq * 8 + i] = kreg[i];
    };
    auto ldV = [&](int kt) {
#pragma unroll
        for (int j = 0; j < 4; j++) {
            int p = vpg * 4 + j;
            float2 v0 = *(const float2*)(Vg + (size_t)(kt * 64 + 2 * p) * 1536 + vdp * 2);
            float2 v1 = *(const float2*)(Vg + (size_t)(kt * 64 + 2 * p + 1) * 1536 + vdp * 2);
            vreg[j * 2]     = pack_bf(v0.x, v1.x);
            vreg[j * 2 + 1] = pack_bf(v0.y, v1.y);
        }
    };
    auto stV = [&](int buf) {
#pragma unroll
        for (int j = 0; j < 4; j++) {
            int p = vpg * 4 + j;
            Vs[buf][vdp * 2][p]     = vreg[j * 2];
            Vs[buf][vdp * 2 + 1][p] = vreg[j * 2 + 1];
        }
    };

    float o[8][4] = {};
    float rs0 = 0.f, rs1 = 0.f;

    ldK(0); ldV(0); stK(0); stV(0);
    __syncthreads();

    for (int kt = 0; kt < 8; kt++) {
        int buf = kt & 1;
        if (kt < 7) { ldK(kt + 1); ldV(kt + 1); }
        uint32_t k_base = (uint32_t)__cvta_generic_to_shared(&Ks[buf][0][0]);
        uint32_t v_base = (uint32_t)__cvta_generic_to_shared(&Vs[buf][0][0]);

        float s[8][4] = {};
#pragma unroll
        for (int ks = 0; ks < 4; ks++) {
            uint32_t kf[8][2];
#pragma unroll
            for (int jp = 0; jp < 4; jp++) {
                uint32_t t4[4];
                ldsm4(t4, k_base + (((jp * 16 + rB) * 36 + ks * 8 + cB) << 2));
                kf[2 * jp][0] = t4[0]; kf[2 * jp][1] = t4[1];
                kf[2 * jp + 1][0] = t4[2]; kf[2 * jp + 1][1] = t4[3];
            }
#pragma unroll
            for (int j = 0; j < 8; j++)
                mma16(s[j], aq[ks], kf[j]);
        }
#pragma unroll
        for (int j = 0; j < 8; j++) {
            s[j][0] = __expf(s[j][0] * 0.125f);
            s[j][1] = __expf(s[j][1] * 0.125f);
            s[j][2] = __expf(s[j][2] * 0.125f);
            s[j][3] = __expf(s[j][3] * 0.125f);
            rs0 += s[j][0] + s[j][1];
            rs1 += s[j][2] + s[j][3];
        }
#pragma unroll
        for (int ks = 0; ks < 4; ks++) {
            uint32_t a[4] = {
                pack_bf(s[2 * ks][0],     s[2 * ks][1]),
                pack_bf(s[2 * ks][2],     s[2 * ks][3]),
                pack_bf(s[2 * ks + 1][0], s[2 * ks + 1][1]),
                pack_bf(s[2 * ks + 1][2], s[2 * ks + 1][3])};
            uint32_t vf[8][2];
#pragma unroll
            for (int jp = 0; jp < 4; jp++) {
                uint32_t t4[4];
                ldsm4(t4, v_base + (((jp * 16 + rB) * 36 + ks * 8 + cB) << 2));
                vf[2 * jp][0] = t4[0]; vf[2 * jp][1] = t4[1];
                vf[2 * jp + 1][0] = t4[2]; vf[2 * jp + 1][1] = t4[3];
            }
#pragma unroll
            for (int j = 0; j < 8; j++)
                mma16(o[j], a, vf[j]);
        }
        if (kt < 7) { stK(buf ^ 1); stV(buf ^ 1); }
        __syncthreads();
    }

    rs0 += __shfl_xor_sync(0xffffffffu, rs0, 1);
    rs0 += __shfl_xor_sync(0xffffffffu, rs0, 2);
    rs1 += __shfl_xor_sync(0xffffffffu, rs1, 1);
    rs1 += __shfl_xor_sync(0xffffffffu, rs1, 2);
    float i0 = 1.f / rs0, i1 = 1.f / rs1;

    float* Og = attn + (size_t)b * MM * HH + (size_t)(qt * 128) * HH + h * 64;
    int r = wm + (lane >> 2);
#pragma unroll
    for (int j = 0; j < 8; j++) {
        int c = j * 8 + (lane & 3) * 2;
        *(float2*)(Og + (size_t)r * HH + c)       = make_float2(o[j][0] * i0, o[j][1] * i0);
        *(float2*)(Og + (size_t)(r + 8) * HH + c) = make_float2(o[j][2] * i1, o[j][3] * i1);
    }
}

// merged lnres + scatter: out[b,idx] = tok[b,idx] + gate * LN(tok[b,idx] + rel)
__global__ void k_lnscatter(const float* __restrict__ tok, float* __restrict__ out,
                            const float* __restrict__ lg, const float* __restrict__ lb) {
    __shared__ float red[4];
    int t = blockIdx.x, tid = threadIdx.x;
    int b = t >> 9;
    int lane = tid & 31, wid = tid >> 5;
    const float* r = g_rel + (size_t)t * HH;
    const float* s = tok + ((size_t)b * NN + g_idx[t]) * HH;
    float* d = out + ((size_t)b * NN + g_idx[t]) * HH;

    float t0 = s[tid],       t1 = s[tid + 128],
          t2 = s[tid + 256], t3 = s[tid + 384];
    float v0 = t0 + r[tid];
    float v1 = t1 + r[tid + 128];
    float v2 = t2 + r[tid + 256];
    float v3 = t3 + r[tid + 384];

    float su = v0 + v1 + v2 + v3;
    float q = v0 * v0 + v1 * v1 + v2 * v2 + v3 * v3;
#pragma unroll
    for (int o = 16; o; o >>= 1) {
        su += __shfl_down_sync(0xffffffffu, su, o);
        q  += __shfl_down_sync(0xffffffffu, q, o);
    }
    if (lane == 0) { red[wid] = su; }
    __syncthreads();
    if (tid == 0) red[0] = red[0] + red[1] + red[2] + red[3];
    __syncthreads();
    float Ssu = red[0];
    __syncthreads();
    if (lane == 0) red[wid] = q;
    __syncthreads();
    if (tid == 0) red[0] = red[0] + red[1] + red[2] + red[3];
    __syncthreads();
    float Sq = red[0];

    float mean = Ssu * (1.f / HH);
    float var = Sq * (1.f / HH) - mean * mean;
    float rstd = rsqrtf(var + LNEPS);
    float gp = g_gate[b];
    d[tid]       = t0 + gp * ((v0 - mean) * rstd * lg[tid]       + lb[tid]);
    d[tid + 128] = t1 + gp * ((v1 - mean) * rstd * lg[tid + 128] + lb[tid + 128]);
    d[tid + 256] = t2 + gp * ((v2 - mean) * rstd * lg[tid + 256] + lb[tid + 256]);
    d[tid + 384] = t3 + gp * ((v3 - mean) * rstd * lg[tid + 384] + lb[tid + 384]);
}

// ---------------- launch ----------------
extern "C" void kernel_launch(void* const* d_in, const int* in_sizes, int n_in,
                              void* d_out, int out_size) {
    const float* tok        = (const float*)d_in[0];
    const float* gate_ln_g  = (const float*)d_in[1];
    const float* gate_ln_b  = (const float*)d_in[2];
    const float* gate_w     = (const float*)d_in[3];
    const float* gate_b     = (const float*)d_in[4];
    const float* sal_ln_g   = (const float*)d_in[5];
    const float* sal_ln_b   = (const float*)d_in[6];
    const float* sal_w      = (const float*)d_in[7];
    const float* sal_b      = (const float*)d_in[8];
    const float* in_proj_w  = (const float*)d_in[9];
    const float* in_proj_b  = (const float*)d_in[10];
    const float* out_proj_w = (const float*)d_in[11];
    const float* out_proj_b = (const float*)d_in[12];
    const float* rel_ln_g   = (const float*)d_in[13];
    const float* rel_ln_b   = (const float*)d_in[14];
    float* out = (float*)d_out;

    void *p_qkv_v, *p_attn_v, *p_rel_v;
    cudaGetSymbolAddress(&p_qkv_v, g_qkv);
    cudaGetSymbolAddress(&p_attn_v, g_attn);
    cudaGetSymbolAddress(&p_rel_v, g_rel);
    float* p_qkv = (float*)p_qkv_v;
    float* p_attn = (float*)p_attn_v;
    float* p_rel = (float*)p_rel_v;

    // fork a side stream for the low-footprint persistent copy
    cudaStream_t s2;
    cudaEvent_t eFork, eCopy;
    cudaStreamCreateWithFlags(&s2, cudaStreamNonBlocking);
    cudaEventCreateWithFlags(&eFork, cudaEventDisableTiming);
    cudaEventCreateWithFlags(&eCopy, cudaEventDisableTiming);

    cudaEventRecord(eFork, 0);
    cudaStreamWaitEvent(s2, eFork, 0);
    k_copy<<<64, 256, 0, s2>>>((const float4*)tok, (float4*)out);
    cudaEventRecord(eCopy, s2);

    k_poolsal<<<dim3(BB, 32), 512>>>(tok, sal_ln_g, sal_ln_b, sal_w, sal_b);
    k_pool2gate<<<BB, 512>>>(gate_ln_g, gate_ln_b, gate_w, gate_b);
    k_topk<<<dim3(BB, NN / 256), 256>>>();

    // qkv = gather(tok)[sel] @ in_proj_w^T + in_proj_b : M=8192, N=1536, K=512
    k_gemm_bf<128, 128, 2, 4, 1><<<dim3(12, 64, 1), 256>>>(
        tok, in_proj_w, in_proj_b, p_qkv, HH, HH, HH, 3 * HH, 1.f);

    // flash attention (S in registers)
    k_attn<<<BB * NHEAD * 4, 256>>>(p_qkv, p_attn);

    // rel = attn_out @ out_proj_w^T + out_proj_b : M=8192, N=512, K=512
    k_gemm_bf<128, 128, 2, 4, 0><<<dim3(4, 64, 1), 256>>>(
        p_attn, out_proj_w, out_proj_b, p_rel, HH, HH, HH, HH, 1.f);

    // join: the scatter overwrites selected rows after the copy has run
    cudaStreamWaitEvent(0, eCopy, 0);
    k_lnscatter<<<BB * MM, 128>>>(tok, out, rel_ln_g, rel_ln_b);
}

// round 15
// speedup vs baseline: 1.1534x; 1.1534x over previous
#include <cuda_runtime.h>
#include <cuda_bf16.h>
#include <stdint.h>
#include <math.h>

#define BB 16
#define NN 4096
#define HH 512
#define NHEAD 8
#define MM 512
#define LNEPS 1e-5f

// ---------------- static scratch (no allocations allowed) ----------------
__device__ float g_ppart[BB * 32 * HH];
__device__ float g_gate[BB];
__device__ float g_sal[BB * NN];
__device__ int   g_idx[BB * MM];
__device__ float g_qkv[(size_t)BB * MM * 3 * HH];
__device__ float g_attn[(size_t)BB * MM * HH];
__device__ float g_rel[(size_t)BB * MM * HH];

// ---------------- small kernels ----------------
// persistent grid-stride copy: 64 CTAs only, coexists with the compute chain
__global__ void k_copy(const float4* __restrict__ tok, float4* __restrict__ out) {
    const size_t n = (size_t)BB * NN * HH / 4;
    size_t stride = (size_t)gridDim.x * blockDim.x;
    size_t i = (size_t)blockIdx.x * blockDim.x + threadIdx.x;
#pragma unroll 4
    for (; i < n; i += stride) out[i] = tok[i];
}

// fused pooled-partials + salience, one token pass, warp-per-token reduction.
__global__ void __launch_bounds__(512)
k_poolsal(const float* __restrict__ tok,
          const float* __restrict__ lg, const float* __restrict__ lb,
          const float* __restrict__ w, const float* __restrict__ wb) {
    __shared__ float tile[16][512];
    __shared__ float gw[512];
    __shared__ float red[32];
    __shared__ float sS[2];
    int b = blockIdx.x, c = blockIdx.y;
    int tid = threadIdx.x, lane = tid & 31, wid = tid >> 5;

    float gwv = lg[tid] * w[tid];
    float bwv = lb[tid] * w[tid];
    gw[tid] = gwv;
    {
        float a0 = gwv, a1 = bwv;
#pragma unroll
        for (int o = 16; o; o >>= 1) {
            a0 += __shfl_down_sync(0xffffffffu, a0, o);
            a1 += __shfl_down_sync(0xffffffffu, a1, o);
        }
        if (lane == 0) { red[wid] = a0; red[wid + 16] = a1; }
    }
    __syncthreads();
    if (tid == 0) {
        float s0 = 0.f, s1 = 0.f;
#pragma unroll
        for (int k = 0; k < 16; k++) { s0 += red[k]; s1 += red[k + 16]; }
        sS[0] = s0; sS[1] = s1;
    }
    __syncthreads();
    float Sgw = sS[0], S2 = sS[1];

    const float* p = tok + ((size_t)(b * NN + c * 128)) * HH + tid;
    float pool = 0.f;

    for (int t8 = 0; t8 < 8; t8++) {
#pragma unroll
        for (int r = 0; r < 16; r++) {
            float x = p[(size_t)(t8 * 16 + r) * HH];
            tile[r][tid] = x;
            pool += x;
        }
        __syncthreads();
        {
            float Sx = 0.f, Sxx = 0.f, Sxg = 0.f;
#pragma unroll
            for (int i = 0; i < 16; i++) {
                float x = tile[wid][lane + 32 * i];
                Sx += x; Sxx += x * x; Sxg += x * gw[lane + 32 * i];
            }
#pragma unroll
            for (int o = 16; o; o >>= 1) {
                Sx  += __shfl_down_sync(0xffffffffu, Sx, o);
                Sxx += __shfl_down_sync(0xffffffffu, Sxx, o);
                Sxg += __shfl_down_sync(0xffffffffu, Sxg, o);
            }
            if (lane == 0) {
                float mean = Sx * (1.f / HH);
                float var = Sxx * (1.f / HH) - mean * mean;
                float rstd = rsqrtf(var + LNEPS);
                g_sal[b * NN + c * 128 + t8 * 16 + wid] =
                    rstd * (Sxg - mean * Sgw) + S2 + wb[0];
            }
        }
        __syncthreads();
    }
    g_ppart[(b * 32 + c) * HH + tid] = pool;
}

// merged pool2 + gate: one block per batch, 512 threads
__global__ void __launch_bounds__(512)
k_pool2gate(const float* __restrict__ lg, const float* __restrict__ lb,
            const float* __restrict__ w, const float* __restrict__ wb) {
    __shared__ float red[16];
    int b = blockIdx.x, tid = threadIdx.x, lane = tid & 31, wid = tid >> 5;
    float s = 0.f;
#pragma unroll
    for (int c = 0; c < 32; c++) s += g_ppart[(b * 32 + c) * HH + tid];
    float v = s * (1.f / NN);

    float a0 = v, a1 = v * v;
#pragma unroll
    for (int o = 16; o; o >>= 1) {
        a0 += __shfl_down_sync(0xffffffffu, a0, o);
        a1 += __shfl_down_sync(0xffffffffu, a1, o);
    }
    if (lane == 0) red[wid] = a0;
    __syncthreads();
    float Sx = 0.f;
    if (tid == 0) {
#pragma unroll
        for (int k = 0; k < 16; k++) Sx += red[k];
        red[0] = Sx;
    }
    __syncthreads();
    Sx = red[0];
    __syncthreads();
    if (lane == 0) red[wid] = a1;
    __syncthreads();
    float Sxx = 0.f;
    if (tid == 0) {
#pragma unroll
        for (int k = 0; k < 16; k++) Sxx += red[k];
        red[0] = Sxx;
    }
    __syncthreads();
    Sxx = red[0];
    __syncthreads();

    float mean = Sx * (1.f / HH);
    float var = Sxx * (1.f / HH) - mean * mean;
    float rstd = rsqrtf(var + LNEPS);
    float d = ((v - mean) * rstd * lg[tid] + lb[tid]) * w[tid];
#pragma unroll
    for (int o = 16; o; o >>= 1) d += __shfl_down_sync(0xffffffffu, d, o);
    if (lane == 0) red[wid] = d;
    __syncthreads();
    if (tid == 0) {
        float dd = 0.f;
#pragma unroll
        for (int k = 0; k < 16; k++) dd += red[k];
        g_gate[b] = 1.f / (1.f + expf(-(dd + wb[0])));
    }
}

// ---------------- radix-select top-512 (one block per batch) ----------------
// Exact: finds 512th-largest key T + tie quota; selects key>T plus first
// (by index) quota tokens with key==T. Slots assigned in index order by scan.
__global__ void __launch_bounds__(512)
k_topk() {
    __shared__ uint32_t keys[NN];
    __shared__ int hist[256];
    __shared__ int hsel[2];
    __shared__ int wsum[16];
    int b = blockIdx.x, tid = threadIdx.x, lane = tid & 31, wid = tid >> 5;

    // load + order-preserving transform
    for (int j = tid; j < NN; j += 512) {
        uint32_t u = __float_as_uint(g_sal[b * NN + j]);
        keys[j] = (u & 0x80000000u) ? ~u : (u | 0x80000000u);
    }
    __syncthreads();

    // 4-pass radix descent (high byte first)
    uint32_t prefix = 0;
    int kneed = MM;
#pragma unroll
    for (int shift = 24; shift >= 0; shift -= 8) {
        if (tid < 256) hist[tid] = 0;
        __syncthreads();
        uint32_t mask = (shift == 24) ? 0u : (0xFFFFFFFFu << (shift + 8));
        for (int j = tid; j < NN; j += 512) {
            uint32_t u = keys[j];
            if ((u & mask) == prefix)
                atomicAdd(&hist[(u >> shift) & 0xFF], 1);
        }
        __syncthreads();
        if (tid == 0) {
            int acc = 0;
            for (int bin = 255; bin >= 0; bin--) {
                int c = hist[bin];
                if (acc + c >= kneed) { hsel[0] = acc; hsel[1] = bin; break; }
                acc += c;
            }
        }
        __syncthreads();
        prefix |= ((uint32_t)hsel[1] << shift);
        kneed -= hsel[0];
        __syncthreads();
    }
    uint32_t T = prefix;

    // scan of (gt<<16 | eq) counts over 8 tokens/thread in index order
    int j0 = tid * 8;
    int local[8];
    int agg = 0;
#pragma unroll
    for (int i = 0; i < 8; i++) {
        uint32_t u = keys[j0 + i];
        local[i] = agg;
        agg += (u > T) ? (1 << 16) : ((u == T) ? 1 : 0);
    }
    // exclusive scan of agg across 512 threads
    int v = agg;
#pragma unroll
    for (int o = 1; o < 32; o <<= 1) {
        int n = __shfl_up_sync(0xffffffffu, v, o);
        if (lane >= o) v += n;
    }
    if (lane == 31) wsum[wid] = v;
    __syncthreads();
    if (tid == 0) {
        int acc = 0;
#pragma unroll
        for (int k = 0; k < 16; k++) { int t = wsum[k]; wsum[k] = acc; acc += t; }
    }
    __syncthreads();
    int base = wsum[wid] + (v - agg);

#pragma unroll
    for (int i = 0; i < 8; i++) {
        uint32_t u = keys[j0 + i];
        int pre = base + local[i];
        int gtb = pre >> 16, eqb = pre & 0xFFFF;
        bool sel = (u > T) || (u == T && eqb < kneed);
        if (sel) {
            int slot = gtb + (eqb < kneed ? eqb : kneed);
            g_idx[b * MM + slot] = j0 + i;
        }
    }
}

// ---------------- BF16 mma / ldmatrix helpers ----------------
__device__ __forceinline__ uint32_t pack_bf(float lo, float hi) {
    __nv_bfloat162 h = __floats2bfloat162_rn(lo, hi);
    return *reinterpret_cast<uint32_t*>(&h);
}

__device__ __forceinline__ void mma16(float* d, const uint32_t* a, const uint32_t* b) {
    asm volatile(
        "mma.sync.aligned.m16n8k16.row.col.f32.bf16.bf16.f32 "
        "{%0,%1,%2,%3}, {%4,%5,%6,%7}, {%8,%9}, {%0,%1,%2,%3};"
        : "+f"(d[0]), "+f"(d[1]), "+f"(d[2]), "+f"(d[3])
        : "r"(a[0]), "r"(a[1]), "r"(a[2]), "r"(a[3]), "r"(b[0]), "r"(b[1]));
}

__device__ __forceinline__ void ldsm4(uint32_t* r, uint32_t saddr) {
    asm volatile(
        "ldmatrix.sync.aligned.m8n8.x4.shared.b16 {%0,%1,%2,%3}, [%4];"
        : "=r"(r[0]), "=r"(r[1]), "=r"(r[2]), "=r"(r[3]) : "r"(saddr));
}

// ---------------- BF16 tensor-core GEMM (double-buffered, ldmatrix) ----------------
template <int MT, int NT, int BWM, int BWN, int GATHER>
__global__ void __launch_bounds__(256, 2)
k_gemm_bf(const float* __restrict__ A, const float* __restrict__ B,
          const float* __restrict__ bias, float* __restrict__ C,
          int K, int lda, int ldb, int ldc, float scale) {
    constexpr int WM = MT / BWM, WN = NT / BWN;
    constexpr int AM = WM / 16, BN = WN / 8;
    constexpr int NA = MT / 32, NB = NT / 32;
    __shared__ uint32_t As[2][MT][20];
    __shared__ uint32_t Bs[2][NT][20];

    int m0 = blockIdx.y * MT, n0 = blockIdx.x * NT;
    int tid = threadIdx.x, lane = tid & 31, wid = tid >> 5;
    int wm = (wid / BWN) * WM, wn = (wid % BWN) * WN;

    float acc[AM][BN][4];
#pragma unroll
    for (int i = 0; i < AM; i++)
#pragma unroll
        for (int j = 0; j < BN; j++) {
            acc[i][j][0] = 0.f; acc[i][j][1] = 0.f;
            acc[i][j][2] = 0.f; acc[i][j][3] = 0.f;
        }

    int lr = tid >> 3;
    int lk = (tid & 7) << 2;
    int lc = (tid & 7) << 1;

    int mi = lane >> 3;
    int rA = (lane & 7) + ((mi & 1) << 3);
    int cA = (mi >> 1) << 2;
    int rB = (lane & 7) + ((mi >> 1) << 3);
    int cB = (mi & 1) << 2;

    const float* arow[NA];
#pragma unroll
    for (int i = 0; i < NA; i++) {
        int r = m0 + lr + 32 * i;
        if (GATHER)
            arow[i] = A + ((size_t)(r >> 9) * NN + g_idx[r]) * HH;
        else
            arow[i] = A + (size_t)r * lda;
    }

    float4 ar[NA], br[NB];

    auto loadT = [&](int k0) {
#pragma unroll
        for (int i = 0; i < NA; i++)
            ar[i] = *(const float4*)(arow[i] + k0 + lk);
#pragma unroll
        for (int i = 0; i < NB; i++)
            br[i] = *(const float4*)(B + (long)(n0 + lr + 32 * i) * ldb + k0 + lk);
    };
    auto storeT = [&](int buf) {
#pragma unroll
        for (int i = 0; i < NA; i++) {
            As[buf][lr + 32 * i][lc]     = pack_bf(ar[i].x, ar[i].y);
            As[buf][lr + 32 * i][lc + 1] = pack_bf(ar[i].z, ar[i].w);
        }
#pragma unroll
        for (int i = 0; i < NB; i++) {
            Bs[buf][lr + 32 * i][lc]     = pack_bf(br[i].x, br[i].y);
            Bs[buf][lr + 32 * i][lc + 1] = pack_bf(br[i].z, br[i].w);
        }
    };

    int nk = K >> 5;
    loadT(0);
    storeT(0);
    __syncthreads();

    for (int kt = 0; kt < nk; kt++) {
        int buf = kt & 1;
        if (kt + 1 < nk) loadT((kt + 1) << 5);
        uint32_t a_base = (uint32_t)__cvta_generic_to_shared(&As[buf][0][0]);
        uint32_t b_base = (uint32_t)__cvta_generic_to_shared(&Bs[buf][0][0]);
#pragma unroll
        for (int ks = 0; ks < 2; ks++) {
            int kc = ks * 8;
            uint32_t af[AM][4];
#pragma unroll
            for (int i = 0; i < AM; i++)
                ldsm4(af[i], a_base + (((wm + i * 16 + rA) * 20 + kc + cA) << 2));
            uint32_t bfr[BN][2];
#pragma unroll
            for (int jp = 0; jp < BN / 2; jp++) {
                uint32_t t4[4];
                ldsm4(t4, b_base + (((wn + jp * 16 + rB) * 20 + kc + cB) << 2));
                bfr[2 * jp][0] = t4[0]; bfr[2 * jp][1] = t4[1];
                bfr[2 * jp + 1][0] = t4[2]; bfr[2 * jp + 1][1] = t4[3];
            }
#pragma unroll
            for (int i = 0; i < AM; i++)
#pragma unroll
                for (int j = 0; j < BN; j++)
                    mma16(acc[i][j], af[i], bfr[j]);
        }
        if (kt + 1 < nk) storeT(buf ^ 1);
        __syncthreads();
    }

#pragma unroll
    for (int i = 0; i < AM; i++) {
        int r0 = m0 + wm + i * 16 + (lane >> 2);
#pragma unroll
        for (int j = 0; j < BN; j++) {
            int c0 = n0 + wn + j * 8 + ((lane & 3) << 1);
            float b0 = 0.f, b1 = 0.f;
            if (bias) { b0 = bias[c0]; b1 = bias[c0 + 1]; }
            float2 o0, o1;
            o0.x = acc[i][j][0] * scale + b0;
            o0.y = acc[i][j][1] * scale + b1;
            o1.x = acc[i][j][2] * scale + b0;
            o1.y = acc[i][j][3] * scale + b1;
            *(float2*)(C + (long)r0 * ldc + c0) = o0;
            *(float2*)(C + (long)(r0 + 8) * ldc + c0) = o1;
        }
    }
}

// ---------------- flash attention (ldmatrix fragments) ----------------
__global__ void __launch_bounds__(256, 2)
k_attn(const float* __restrict__ qkv, float* __restrict__ attn) {
    __shared__ uint32_t Ks[2][64][36];
    __shared__ uint32_t Vs[2][64][36];

    int z = blockIdx.x;
    int qt = z & 3, bh = z >> 2;
    int b = bh >> 3, h = bh & 7;
    int tid = threadIdx.x, lane = tid & 31, wid = tid >> 5;

    const float* base = qkv + (size_t)b * MM * 1536;
    const float* Qg = base + (size_t)(qt * 128) * 1536 + h * 64;
    const float* Kg = base + 512 + h * 64;
    const float* Vg = base + 1024 + h * 64;

    uint32_t* Ksf = &Ks[0][0][0];

    int mi = lane >> 3;
    int rA = (lane & 7) + ((mi & 1) << 3);
    int cA = (mi >> 1) << 2;
    int rB = (lane & 7) + ((mi >> 1) << 3);
    int cB = (mi & 1) << 2;

    {
        int r = tid >> 1, ch = (tid & 1) * 32;
        const float* qp = Qg + (size_t)r * 1536 + ch;
        int o = r * 36 + ch / 2;
#pragma unroll
        for (int i = 0; i < 8; i++) {
            float4 v = *(const float4*)(qp + i * 4);
            Ksf[o + i * 2]     = pack_bf(v.x, v.y);
            Ksf[o + i * 2 + 1] = pack_bf(v.z, v.w);
        }
    }
    __syncthreads();

    int wm = wid * 16;
    uint32_t aq[4][4];
    {
        uint32_t q_base = (uint32_t)__cvta_generic_to_shared(Ksf);
#pragma unroll
        for (int ks = 0; ks < 4; ks++)
            ldsm4(aq[ks], q_base + (((wm + rA) * 36 + ks * 8 + cA) << 2));
    }
    __syncthreads();

    int krow = tid >> 2, kq = tid & 3;
    int vdp = tid & 31, vpg = tid >> 5;
    uint32_t kreg[8], vreg[8];

    auto ldK = [&](int kt) {
        const float* kp = Kg + (size_t)(kt * 64 + krow) * 1536 + kq * 16;
#pragma unroll
        for (int i = 0; i < 4; i++) {
            float4 v = *(const float4*)(kp + i * 4);
            kreg[i * 2]     = pack_bf(v.x, v.y);
            kreg[i * 2 + 1] = pack_bf(v.z, v.w);
        }
    };
    auto stK = [&](int buf) {
#pragma unroll
        for (int i = 0; i < 8; i++) Ks[buf][krow][kq * 8 + i] = kreg[i];
    };
    auto ldV = [&](int kt) {
#pragma unroll
        for (int j = 0; j < 4; j++) {
            int p = vpg * 4 + j;
            float2 v0 = *(const float2*)(Vg + (size_t)(kt * 64 + 2 * p) * 1536 + vdp * 2);
            float2 v1 = *(const float2*)(Vg + (size_t)(kt * 64 + 2 * p + 1) * 1536 + vdp * 2);
            vreg[j * 2]     = pack_bf(v0.x, v1.x);
            vreg[j * 2 + 1] = pack_bf(v0.y, v1.y);
        }
    };
    auto stV = [&](int buf) {
#pragma unroll
        for (int j = 0; j < 4; j++) {
            int p = vpg * 4 + j;
            Vs[buf][vdp * 2][p]     = vreg[j * 2];
            Vs[buf][vdp * 2 + 1][p] = vreg[j * 2 + 1];
        }
    };

    float o[8][4] = {};
    float rs0 = 0.f, rs1 = 0.f;

    ldK(0); ldV(0); stK(0); stV(0);
    __syncthreads();

    for (int kt = 0; kt < 8; kt++) {
        int buf = kt & 1;
        if (kt < 7) { ldK(kt + 1); ldV(kt + 1); }
        uint32_t k_base = (uint32_t)__cvta_generic_to_shared(&Ks[buf][0][0]);
        uint32_t v_base = (uint32_t)__cvta_generic_to_shared(&Vs[buf][0][0]);

        float s[8][4] = {};
#pragma unroll
        for (int ks = 0; ks < 4; ks++) {
            uint32_t kf[8][2];
#pragma unroll
            for (int jp = 0; jp < 4; jp++) {
                uint32_t t4[4];
                ldsm4(t4, k_base + (((jp * 16 + rB) * 36 + ks * 8 + cB) << 2));
                kf[2 * jp][0] = t4[0]; kf[2 * jp][1] = t4[1];
                kf[2 * jp + 1][0] = t4[2]; kf[2 * jp + 1][1] = t4[3];
            }
#pragma unroll
            for (int j = 0; j < 8; j++)
                mma16(s[j], aq[ks], kf[j]);
        }
#pragma unroll
        for (int j = 0; j < 8; j++) {
            s[j][0] = __expf(s[j][0] * 0.125f);
            s[j][1] = __expf(s[j][1] * 0.125f);
            s[j][2] = __expf(s[j][2] * 0.125f);
            s[j][3] = __expf(s[j][3] * 0.125f);
            rs0 += s[j][0] + s[j][1];
            rs1 += s[j][2] + s[j][3];
        }
#pragma unroll
        for (int ks = 0; ks < 4; ks++) {
            uint32_t a[4] = {
                pack_bf(s[2 * ks][0],     s[2 * ks][1]),
                pack_bf(s[2 * ks][2],     s[2 * ks][3]),
                pack_bf(s[2 * ks + 1][0], s[2 * ks + 1][1]),
                pack_bf(s[2 * ks + 1][2], s[2 * ks + 1][3])};
            uint32_t vf[8][2];
#pragma unroll
            for (int jp = 0; jp < 4; jp++) {
                uint32_t t4[4];
                ldsm4(t4, v_base + (((jp * 16 + rB) * 36 + ks * 8 + cB) << 2));
                vf[2 * jp][0] = t4[0]; vf[2 * jp][1] = t4[1];
                vf[2 * jp + 1][0] = t4[2]; vf[2 * jp + 1][1] = t4[3];
            }
#pragma unroll
            for (int j = 0; j < 8; j++)
                mma16(o[j], a, vf[j]);
        }
        if (kt < 7) { stK(buf ^ 1); stV(buf ^ 1); }
        __syncthreads();
    }

    rs0 += __shfl_xor_sync(0xffffffffu, rs0, 1);
    rs0 += __shfl_xor_sync(0xffffffffu, rs0, 2);
    rs1 += __shfl_xor_sync(0xffffffffu, rs1, 1);
    rs1 += __shfl_xor_sync(0xffffffffu, rs1, 2);
    float i0 = 1.f / rs0, i1 = 1.f / rs1;

    float* Og = attn + (size_t)b * MM * HH + (size_t)(qt * 128) * HH + h * 64;
    int r = wm + (lane >> 2);
#pragma unroll
    for (int j = 0; j < 8; j++) {
        int c = j * 8 + (lane & 3) * 2;
        *(float2*)(Og + (size_t)r * HH + c)       = make_float2(o[j][0] * i0, o[j][1] * i0);
        *(float2*)(Og + (size_t)(r + 8) * HH + c) = make_float2(o[j][2] * i1, o[j][3] * i1);
    }
}

// merged lnres + scatter: out[b,idx] = tok[b,idx] + gate * LN(tok[b,idx] + rel)
__global__ void k_lnscatter(const float* __restrict__ tok, float* __restrict__ out,
                            const float* __restrict__ lg, const float* __restrict__ lb) {
    __shared__ float red[4];
    int t = blockIdx.x, tid = threadIdx.x;
    int b = t >> 9;
    int lane = tid & 31, wid = tid >> 5;
    const float* r = g_rel + (size_t)t * HH;
    const float* s = tok + ((size_t)b * NN + g_idx[t]) * HH;
    float* d = out + ((size_t)b * NN + g_idx[t]) * HH;

    float t0 = s[tid],       t1 = s[tid + 128],
          t2 = s[tid + 256], t3 = s[tid + 384];
    float v0 = t0 + r[tid];
    float v1 = t1 + r[tid + 128];
    float v2 = t2 + r[tid + 256];
    float v3 = t3 + r[tid + 384];

    float su = v0 + v1 + v2 + v3;
    float q = v0 * v0 + v1 * v1 + v2 * v2 + v3 * v3;
#pragma unroll
    for (int o = 16; o; o >>= 1) {
        su += __shfl_down_sync(0xffffffffu, su, o);
        q  += __shfl_down_sync(0xffffffffu, q, o);
    }
    if (lane == 0) { red[wid] = su; }
    __syncthreads();
    if (tid == 0) red[0] = red[0] + red[1] + red[2] + red[3];
    __syncthreads();
    float Ssu = red[0];
    __syncthreads();
    if (lane == 0) red[wid] = q;
    __syncthreads();
    if (tid == 0) red[0] = red[0] + red[1] + red[2] + red[3];
    __syncthreads();
    float Sq = red[0];

    float mean = Ssu * (1.f / HH);
    float var = Sq * (1.f / HH) - mean * mean;
    float rstd = rsqrtf(var + LNEPS);
    float gp = g_gate[b];
    d[tid]       = t0 + gp * ((v0 - mean) * rstd * lg[tid]       + lb[tid]);
    d[tid + 128] = t1 + gp * ((v1 - mean) * rstd * lg[tid + 128] + lb[tid + 128]);
    d[tid + 256] = t2 + gp * ((v2 - mean) * rstd * lg[tid + 256] + lb[tid + 256]);
    d[tid + 384] = t3 + gp * ((v3 - mean) * rstd * lg[tid + 384] + lb[tid + 384]);
}

// ---------------- launch ----------------
extern "C" void kernel_launch(void* const* d_in, const int* in_sizes, int n_in,
                              void* d_out, int out_size) {
    const float* tok        = (const float*)d_in[0];
    const float* gate_ln_g  = (const float*)d_in[1];
    const float* gate_ln_b  = (const float*)d_in[2];
    const float* gate_w     = (const float*)d_in[3];
    const float* gate_b     = (const float*)d_in[4];
    const float* sal_ln_g   = (const float*)d_in[5];
    const float* sal_ln_b   = (const float*)d_in[6];
    const float* sal_w      = (const float*)d_in[7];
    const float* sal_b      = (const float*)d_in[8];
    const float* in_proj_w  = (const float*)d_in[9];
    const float* in_proj_b  = (const float*)d_in[10];
    const float* out_proj_w = (const float*)d_in[11];
    const float* out_proj_b = (const float*)d_in[12];
    const float* rel_ln_g   = (const float*)d_in[13];
    const float* rel_ln_b   = (const float*)d_in[14];
    float* out = (float*)d_out;

    void *p_qkv_v, *p_attn_v, *p_rel_v;
    cudaGetSymbolAddress(&p_qkv_v, g_qkv);
    cudaGetSymbolAddress(&p_attn_v, g_attn);
    cudaGetSymbolAddress(&p_rel_v, g_rel);
    float* p_qkv = (float*)p_qkv_v;
    float* p_attn = (float*)p_attn_v;
    float* p_rel = (float*)p_rel_v;

    // fork a side stream for the low-footprint persistent copy
    cudaStream_t s2;
    cudaEvent_t eFork, eCopy;
    cudaStreamCreateWithFlags(&s2, cudaStreamNonBlocking);
    cudaEventCreateWithFlags(&eFork, cudaEventDisableTiming);
    cudaEventCreateWithFlags(&eCopy, cudaEventDisableTiming);

    cudaEventRecord(eFork, 0);
    cudaStreamWaitEvent(s2, eFork, 0);
    k_copy<<<64, 256, 0, s2>>>((const float4*)tok, (float4*)out);
    cudaEventRecord(eCopy, s2);

    k_poolsal<<<dim3(BB, 32), 512>>>(tok, sal_ln_g, sal_ln_b, sal_w, sal_b);
    k_pool2gate<<<BB, 512>>>(gate_ln_g, gate_ln_b, gate_w, gate_b);
    k_topk<<<BB, 512>>>();

    // qkv = gather(tok)[sel] @ in_proj_w^T + in_proj_b : M=8192, N=1536, K=512
    k_gemm_bf<128, 128, 2, 4, 1><<<dim3(12, 64, 1), 256>>>(
        tok, in_proj_w, in_proj_b, p_qkv, HH, HH, HH, 3 * HH, 1.f);

    // flash attention (S in registers)
    k_attn<<<BB * NHEAD * 4, 256>>>(p_qkv, p_attn);

    // rel = attn_out @ out_proj_w^T + out_proj_b : M=8192, N=512, K=512
    k_gemm_bf<128, 128, 2, 4, 0><<<dim3(4, 64, 1), 256>>>(
        p_attn, out_proj_w, out_proj_b, p_rel, HH, HH, HH, HH, 1.f);

    // join: the scatter overwrites selected rows after the copy has run
    cudaStreamWaitEvent(0, eCopy, 0);
    k_lnscatter<<<BB * MM, 128>>>(tok, out, rel_ln_g, rel_ln_b);
}

// round 17
// speedup vs baseline: 1.2369x; 1.0724x over previous
#include <cuda_runtime.h>
#include <cuda_bf16.h>
#include <stdint.h>
#include <math.h>

#define BB 16
#define NN 4096
#define HH 512
#define NHEAD 8
#define MM 512
#define LNEPS 1e-5f

// ---------------- static scratch (no allocations allowed) ----------------
__device__ float g_ppart[BB * 32 * HH];
__device__ float g_gate[BB];
__device__ float g_sal[BB * NN];
__device__ int   g_idx[BB * MM];
__device__ float g_qkv[(size_t)BB * MM * 3 * HH];
__device__ float g_attn[(size_t)BB * MM * HH];
__device__ float g_rel[(size_t)BB * MM * HH];

// ---------------- small kernels ----------------
// persistent grid-stride copy: 64 CTAs only, coexists with the compute chain
__global__ void k_copy(const float4* __restrict__ tok, float4* __restrict__ out) {
    const size_t n = (size_t)BB * NN * HH / 4;
    size_t stride = (size_t)gridDim.x * blockDim.x;
    size_t i = (size_t)blockIdx.x * blockDim.x + threadIdx.x;
#pragma unroll 4
    for (; i < n; i += stride) out[i] = tok[i];
}

// fused pooled-partials + salience, one token pass, warp-per-token reduction.
__global__ void __launch_bounds__(512)
k_poolsal(const float* __restrict__ tok,
          const float* __restrict__ lg, const float* __restrict__ lb,
          const float* __restrict__ w, const float* __restrict__ wb) {
    __shared__ float tile[16][512];
    __shared__ float gw[512];
    __shared__ float red[32];
    __shared__ float sS[2];
    int b = blockIdx.x, c = blockIdx.y;
    int tid = threadIdx.x, lane = tid & 31, wid = tid >> 5;

    float gwv = lg[tid] * w[tid];
    float bwv = lb[tid] * w[tid];
    gw[tid] = gwv;
    {
        float a0 = gwv, a1 = bwv;
#pragma unroll
        for (int o = 16; o; o >>= 1) {
            a0 += __shfl_down_sync(0xffffffffu, a0, o);
            a1 += __shfl_down_sync(0xffffffffu, a1, o);
        }
        if (lane == 0) { red[wid] = a0; red[wid + 16] = a1; }
    }
    __syncthreads();
    if (tid == 0) {
        float s0 = 0.f, s1 = 0.f;
#pragma unroll
        for (int k = 0; k < 16; k++) { s0 += red[k]; s1 += red[k + 16]; }
        sS[0] = s0; sS[1] = s1;
    }
    __syncthreads();
    float Sgw = sS[0], S2 = sS[1];

    const float* p = tok + ((size_t)(b * NN + c * 128)) * HH + tid;
    float pool = 0.f;

    for (int t8 = 0; t8 < 8; t8++) {
#pragma unroll
        for (int r = 0; r < 16; r++) {
            float x = p[(size_t)(t8 * 16 + r) * HH];
            tile[r][tid] = x;
            pool += x;
        }
        __syncthreads();
        {
            float Sx = 0.f, Sxx = 0.f, Sxg = 0.f;
#pragma unroll
            for (int i = 0; i < 16; i++) {
                float x = tile[wid][lane + 32 * i];
                Sx += x; Sxx += x * x; Sxg += x * gw[lane + 32 * i];
            }
#pragma unroll
            for (int o = 16; o; o >>= 1) {
                Sx  += __shfl_down_sync(0xffffffffu, Sx, o);
                Sxx += __shfl_down_sync(0xffffffffu, Sxx, o);
                Sxg += __shfl_down_sync(0xffffffffu, Sxg, o);
            }
            if (lane == 0) {
                float mean = Sx * (1.f / HH);
                float var = Sxx * (1.f / HH) - mean * mean;
                float rstd = rsqrtf(var + LNEPS);
                g_sal[b * NN + c * 128 + t8 * 16 + wid] =
                    rstd * (Sxg - mean * Sgw) + S2 + wb[0];
            }
        }
        __syncthreads();
    }
    g_ppart[(b * 32 + c) * HH + tid] = pool;
}

// merged pool2 + gate: one block per batch, 512 threads
__global__ void __launch_bounds__(512)
k_pool2gate(const float* __restrict__ lg, const float* __restrict__ lb,
            const float* __restrict__ w, const float* __restrict__ wb) {
    __shared__ float red[16];
    int b = blockIdx.x, tid = threadIdx.x, lane = tid & 31, wid = tid >> 5;
    float s = 0.f;
#pragma unroll
    for (int c = 0; c < 32; c++) s += g_ppart[(b * 32 + c) * HH + tid];
    float v = s * (1.f / NN);

    float a0 = v, a1 = v * v;
#pragma unroll
    for (int o = 16; o; o >>= 1) {
        a0 += __shfl_down_sync(0xffffffffu, a0, o);
        a1 += __shfl_down_sync(0xffffffffu, a1, o);
    }
    if (lane == 0) red[wid] = a0;
    __syncthreads();
    float Sx = 0.f;
    if (tid == 0) {
#pragma unroll
        for (int k = 0; k < 16; k++) Sx += red[k];
        red[0] = Sx;
    }
    __syncthreads();
    Sx = red[0];
    __syncthreads();
    if (lane == 0) red[wid] = a1;
    __syncthreads();
    float Sxx = 0.f;
    if (tid == 0) {
#pragma unroll
        for (int k = 0; k < 16; k++) Sxx += red[k];
        red[0] = Sxx;
    }
    __syncthreads();
    Sxx = red[0];
    __syncthreads();

    float mean = Sx * (1.f / HH);
    float var = Sxx * (1.f / HH) - mean * mean;
    float rstd = rsqrtf(var + LNEPS);
    float d = ((v - mean) * rstd * lg[tid] + lb[tid]) * w[tid];
#pragma unroll
    for (int o = 16; o; o >>= 1) d += __shfl_down_sync(0xffffffffu, d, o);
    if (lane == 0) red[wid] = d;
    __syncthreads();
    if (tid == 0) {
        float dd = 0.f;
#pragma unroll
        for (int k = 0; k < 16; k++) dd += red[k];
        g_gate[b] = 1.f / (1.f + expf(-(dd + wb[0])));
    }
}

// ---------------- radix-select top-512 (one block per batch) ----------------
// Parallel bin-select: suffix scan of the 256-bin histogram (uniform barriers).
__global__ void __launch_bounds__(512)
k_topk() {
    __shared__ uint32_t keys[NN];
    __shared__ int hist[256];
    __shared__ int hsel[2];
    __shared__ int wred[16];
    __shared__ int wsum[16];
    int b = blockIdx.x, tid = threadIdx.x, lane = tid & 31, wid = tid >> 5;

    // load + order-preserving transform
    for (int j = tid; j < NN; j += 512) {
        uint32_t u = __float_as_uint(g_sal[b * NN + j]);
        keys[j] = (u & 0x80000000u) ? ~u : (u | 0x80000000u);
    }
    __syncthreads();

    // 4-pass radix descent (high byte first)
    uint32_t prefix = 0;
    int kneed = MM;
#pragma unroll
    for (int shift = 24; shift >= 0; shift -= 8) {
        if (tid < 256) hist[tid] = 0;
        __syncthreads();
        uint32_t mask = (shift == 24) ? 0u : (0xFFFFFFFFu << (shift + 8));
        for (int j = tid; j < NN; j += 512) {
            uint32_t u = keys[j];
            if ((u & mask) == prefix)
                atomicAdd(&hist[(u >> shift) & 0xFF], 1);
        }
        __syncthreads();

        // suffix scan over bins: thread t (t<256) handles bin 255-t.
        int val = (tid < 256) ? hist[255 - tid] : 0;
        int incl = val;
#pragma unroll
        for (int o = 1; o < 32; o <<= 1) {
            int n = __shfl_up_sync(0xffffffffu, incl, o);
            if (lane >= o) incl += n;
        }
        if (lane == 31 && wid < 8) wred[wid] = incl;
        __syncthreads();
        if (tid == 0) {
            int acc = 0;
#pragma unroll
            for (int k = 0; k < 8; k++) { int t = wred[k]; wred[k] = acc; acc += t; }
        }
        __syncthreads();
        if (tid < 256) {
            incl += wred[wid];
            int excl = incl - val;
            if (incl >= kneed && excl < kneed) {
                hsel[0] = excl;            // count strictly above this bin
                hsel[1] = 255 - tid;       // selected bin
            }
        }
        __syncthreads();
        prefix |= ((uint32_t)hsel[1] << shift);
        kneed -= hsel[0];
        __syncthreads();
    }
    uint32_t T = prefix;

    // scan of (gt<<16 | eq) counts over 8 tokens/thread in index order
    int j0 = tid * 8;
    int local[8];
    int agg = 0;
#pragma unroll
    for (int i = 0; i < 8; i++) {
        uint32_t u = keys[j0 + i];
        local[i] = agg;
        agg += (u > T) ? (1 << 16) : ((u == T) ? 1 : 0);
    }
    int v = agg;
#pragma unroll
    for (int o = 1; o < 32; o <<= 1) {
        int n = __shfl_up_sync(0xffffffffu, v, o);
        if (lane >= o) v += n;
    }
    if (lane == 31) wsum[wid] = v;
    __syncthreads();
    if (tid == 0) {
        int acc = 0;
#pragma unroll
        for (int k = 0; k < 16; k++) { int t = wsum[k]; wsum[k] = acc; acc += t; }
    }
    __syncthreads();
    int base = wsum[wid] + (v - agg);

#pragma unroll
    for (int i = 0; i < 8; i++) {
        uint32_t u = keys[j0 + i];
        int pre = base + local[i];
        int gtb = pre >> 16, eqb = pre & 0xFFFF;
        bool sel = (u > T) || (u == T && eqb < kneed);
        if (sel) {
            int slot = gtb + (eqb < kneed ? eqb : kneed);
            g_idx[b * MM + slot] = j0 + i;
        }
    }
}

// ---------------- BF16 mma / ldmatrix helpers ----------------
__device__ __forceinline__ uint32_t pack_bf(float lo, float hi) {
    __nv_bfloat162 h = __floats2bfloat162_rn(lo, hi);
    return *reinterpret_cast<uint32_t*>(&h);
}

__device__ __forceinline__ void mma16(float* d, const uint32_t* a, const uint32_t* b) {
    asm volatile(
        "mma.sync.aligned.m16n8k16.row.col.f32.bf16.bf16.f32 "
        "{%0,%1,%2,%3}, {%4,%5,%6,%7}, {%8,%9}, {%0,%1,%2,%3};"
        : "+f"(d[0]), "+f"(d[1]), "+f"(d[2]), "+f"(d[3])
        : "r"(a[0]), "r"(a[1]), "r"(a[2]), "r"(a[3]), "r"(b[0]), "r"(b[1]));
}

__device__ __forceinline__ void ldsm4(uint32_t* r, uint32_t saddr) {
    asm volatile(
        "ldmatrix.sync.aligned.m8n8.x4.shared.b16 {%0,%1,%2,%3}, [%4];"
        : "=r"(r[0]), "=r"(r[1]), "=r"(r[2]), "=r"(r[3]) : "r"(saddr));
}

// ---------------- BF16 tensor-core GEMM (double-buffered, ldmatrix) ----------------
template <int MT, int NT, int BWM, int BWN, int GATHER>
__global__ void __launch_bounds__(256, 2)
k_gemm_bf(const float* __restrict__ A, const float* __restrict__ B,
          const float* __restrict__ bias, float* __restrict__ C,
          int K, int lda, int ldb, int ldc, float scale) {
    constexpr int WM = MT / BWM, WN = NT / BWN;
    constexpr int AM = WM / 16, BN = WN / 8;
    constexpr int NA = MT / 32, NB = NT / 32;
    __shared__ uint32_t As[2][MT][20];
    __shared__ uint32_t Bs[2][NT][20];

    int m0 = blockIdx.y * MT, n0 = blockIdx.x * NT;
    int tid = threadIdx.x, lane = tid & 31, wid = tid >> 5;
    int wm = (wid / BWN) * WM, wn = (wid % BWN) * WN;

    float acc[AM][BN][4];
#pragma unroll
    for (int i = 0; i < AM; i++)
#pragma unroll
        for (int j = 0; j < BN; j++) {
            acc[i][j][0] = 0.f; acc[i][j][1] = 0.f;
            acc[i][j][2] = 0.f; acc[i][j][3] = 0.f;
        }

    int lr = tid >> 3;
    int lk = (tid & 7) << 2;
    int lc = (tid & 7) << 1;

    int mi = lane >> 3;
    int rA = (lane & 7) + ((mi & 1) << 3);
    int cA = (mi >> 1) << 2;
    int rB = (lane & 7) + ((mi >> 1) << 3);
    int cB = (mi & 1) << 2;

    const float* arow[NA];
#pragma unroll
    for (int i = 0; i < NA; i++) {
        int r = m0 + lr + 32 * i;
        if (GATHER)
            arow[i] = A + ((size_t)(r >> 9) * NN + g_idx[r]) * HH;
        else
            arow[i] = A + (size_t)r * lda;
    }

    float4 ar[NA], br[NB];

    auto loadT = [&](int k0) {
#pragma unroll
        for (int i = 0; i < NA; i++)
            ar[i] = *(const float4*)(arow[i] + k0 + lk);
#pragma unroll
        for (int i = 0; i < NB; i++)
            br[i] = *(const float4*)(B + (long)(n0 + lr + 32 * i) * ldb + k0 + lk);
    };
    auto storeT = [&](int buf) {
#pragma unroll
        for (int i = 0; i < NA; i++) {
            As[buf][lr + 32 * i][lc]     = pack_bf(ar[i].x, ar[i].y);
            As[buf][lr + 32 * i][lc + 1] = pack_bf(ar[i].z, ar[i].w);
        }
#pragma unroll
        for (int i = 0; i < NB; i++) {
            Bs[buf][lr + 32 * i][lc]     = pack_bf(br[i].x, br[i].y);
            Bs[buf][lr + 32 * i][lc + 1] = pack_bf(br[i].z, br[i].w);
        }
    };

    int nk = K >> 5;
    loadT(0);
    storeT(0);
    __syncthreads();

    for (int kt = 0; kt < nk; kt++) {
        int buf = kt & 1;
        if (kt + 1 < nk) loadT((kt + 1) << 5);
        uint32_t a_base = (uint32_t)__cvta_generic_to_shared(&As[buf][0][0]);
        uint32_t b_base = (uint32_t)__cvta_generic_to_shared(&Bs[buf][0][0]);
#pragma unroll
        for (int ks = 0; ks < 2; ks++) {
            int kc = ks * 8;
            uint32_t af[AM][4];
#pragma unroll
            for (int i = 0; i < AM; i++)
                ldsm4(af[i], a_base + (((wm + i * 16 + rA) * 20 + kc + cA) << 2));
            uint32_t bfr[BN][2];
#pragma unroll
            for (int jp = 0; jp < BN / 2; jp++) {
                uint32_t t4[4];
                ldsm4(t4, b_base + (((wn + jp * 16 + rB) * 20 + kc + cB) << 2));
                bfr[2 * jp][0] = t4[0]; bfr[2 * jp][1] = t4[1];
                bfr[2 * jp + 1][0] = t4[2]; bfr[2 * jp + 1][1] = t4[3];
            }
#pragma unroll
            for (int i = 0; i < AM; i++)
#pragma unroll
                for (int j = 0; j < BN; j++)
                    mma16(acc[i][j], af[i], bfr[j]);
        }
        if (kt + 1 < nk) storeT(buf ^ 1);
        __syncthreads();
    }

#pragma unroll
    for (int i = 0; i < AM; i++) {
        int r0 = m0 + wm + i * 16 + (lane >> 2);
#pragma unroll
        for (int j = 0; j < BN; j++) {
            int c0 = n0 + wn + j * 8 + ((lane & 3) << 1);
            float b0 = 0.f, b1 = 0.f;
            if (bias) { b0 = bias[c0]; b1 = bias[c0 + 1]; }
            float2 o0, o1;
            o0.x = acc[i][j][0] * scale + b0;
            o0.y = acc[i][j][1] * scale + b1;
            o1.x = acc[i][j][2] * scale + b0;
            o1.y = acc[i][j][3] * scale + b1;
            *(float2*)(C + (long)r0 * ldc + c0) = o0;
            *(float2*)(C + (long)(r0 + 8) * ldc + c0) = o1;
        }
    }
}

// ---------------- flash attention (ldmatrix fragments) ----------------
__global__ void __launch_bounds__(256, 2)
k_attn(const float* __restrict__ qkv, float* __restrict__ attn) {
    __shared__ uint32_t Ks[2][64][36];
    __shared__ uint32_t Vs[2][64][36];

    int z = blockIdx.x;
    int qt = z & 3, bh = z >> 2;
    int b = bh >> 3, h = bh & 7;
    int tid = threadIdx.x, lane = tid & 31, wid = tid >> 5;

    const float* base = qkv + (size_t)b * MM * 1536;
    const float* Qg = base + (size_t)(qt * 128) * 1536 + h * 64;
    const float* Kg = base + 512 + h * 64;
    const float* Vg = base + 1024 + h * 64;

    uint32_t* Ksf = &Ks[0][0][0];

    int mi = lane >> 3;
    int rA = (lane & 7) + ((mi & 1) << 3);
    int cA = (mi >> 1) << 2;
    int rB = (lane & 7) + ((mi >> 1) << 3);
    int cB = (mi & 1) << 2;

    {
        int r = tid >> 1, ch = (tid & 1) * 32;
        const float* qp = Qg + (size_t)r * 1536 + ch;
        int o = r * 36 + ch / 2;
#pragma unroll
        for (int i = 0; i < 8; i++) {
            float4 v = *(const float4*)(qp + i * 4);
            Ksf[o + i * 2]     = pack_bf(v.x, v.y);
            Ksf[o + i * 2 + 1] = pack_bf(v.z, v.w);
        }
    }
    __syncthreads();

    int wm = wid * 16;
    uint32_t aq[4][4];
    {
        uint32_t q_base = (uint32_t)__cvta_generic_to_shared(Ksf);
#pragma unroll
        for (int ks = 0; ks < 4; ks++)
            ldsm4(aq[ks], q_base + (((wm + rA) * 36 + ks * 8 + cA) << 2));
    }
    __syncthreads();

    int krow = tid >> 2, kq = tid & 3;
    int vdp = tid & 31, vpg = tid >> 5;
    uint32_t kreg[8], vreg[8];

    auto ldK = [&](int kt) {
        const float* kp = Kg + (size_t)(kt * 64 + krow) * 1536 + kq * 16;
#pragma unroll
        for (int i = 0; i < 4; i++) {
            float4 v = *(const float4*)(kp + i * 4);
            kreg[i * 2]     = pack_bf(v.x, v.y);
            kreg[i * 2 + 1] = pack_bf(v.z, v.w);
        }
    };
    auto stK = [&](int buf) {
#pragma unroll
        for (int i = 0; i < 8; i++) Ks[buf][krow][kq * 8 + i] = kreg[i];
    };
    auto ldV = [&](int kt) {
#pragma unroll
        for (int j = 0; j < 4; j++) {
            int p = vpg * 4 + j;
            float2 v0 = *(const float2*)(Vg + (size_t)(kt * 64 + 2 * p) * 1536 + vdp * 2);
            float2 v1 = *(const float2*)(Vg + (size_t)(kt * 64 + 2 * p + 1) * 1536 + vdp * 2);
            vreg[j * 2]     = pack_bf(v0.x, v1.x);
            vreg[j * 2 + 1] = pack_bf(v0.y, v1.y);
        }
    };
    auto stV = [&](int buf) {
#pragma unroll
        for (int j = 0; j < 4; j++) {
            int p = vpg * 4 + j;
            Vs[buf][vdp * 2][p]     = vreg[j * 2];
            Vs[buf][vdp * 2 + 1][p] = vreg[j * 2 + 1];
        }
    };

    float o[8][4] = {};
    float rs0 = 0.f, rs1 = 0.f;

    ldK(0); ldV(0); stK(0); stV(0);
    __syncthreads();

    for (int kt = 0; kt < 8; kt++) {
        int buf = kt & 1;
        if (kt < 7) { ldK(kt + 1); ldV(kt + 1); }
        uint32_t k_base = (uint32_t)__cvta_generic_to_shared(&Ks[buf][0][0]);
        uint32_t v_base = (uint32_t)__cvta_generic_to_shared(&Vs[buf][0][0]);

        float s[8][4] = {};
#pragma unroll
        for (int ks = 0; ks < 4; ks++) {
            uint32_t kf[8][2];
#pragma unroll
            for (int jp = 0; jp < 4; jp++) {
                uint32_t t4[4];
                ldsm4(t4, k_base + (((jp * 16 + rB) * 36 + ks * 8 + cB) << 2));
                kf[2 * jp][0] = t4[0]; kf[2 * jp][1] = t4[1];
                kf[2 * jp + 1][0] = t4[2]; kf[2 * jp + 1][1] = t4[3];
            }
#pragma unroll
            for (int j = 0; j < 8; j++)
                mma16(s[j], aq[ks], kf[j]);
        }
#pragma unroll
        for (int j = 0; j < 8; j++) {
            s[j][0] = __expf(s[j][0] * 0.125f);
            s[j][1] = __expf(s[j][1] * 0.125f);
            s[j][2] = __expf(s[j][2] * 0.125f);
            s[j][3] = __expf(s[j][3] * 0.125f);
            rs0 += s[j][0] + s[j][1];
            rs1 += s[j][2] + s[j][3];
        }
#pragma unroll
        for (int ks = 0; ks < 4; ks++) {
            uint32_t a[4] = {
                pack_bf(s[2 * ks][0],     s[2 * ks][1]),
                pack_bf(s[2 * ks][2],     s[2 * ks][3]),
                pack_bf(s[2 * ks + 1][0], s[2 * ks + 1][1]),
                pack_bf(s[2 * ks + 1][2], s[2 * ks + 1][3])};
            uint32_t vf[8][2];
#pragma unroll
            for (int jp = 0; jp < 4; jp++) {
                uint32_t t4[4];
                ldsm4(t4, v_base + (((jp * 16 + rB) * 36 + ks * 8 + cB) << 2));
                vf[2 * jp][0] = t4[0]; vf[2 * jp][1] = t4[1];
                vf[2 * jp + 1][0] = t4[2]; vf[2 * jp + 1][1] = t4[3];
            }
#pragma unroll
            for (int j = 0; j < 8; j++)
                mma16(o[j], a, vf[j]);
        }
        if (kt < 7) { stK(buf ^ 1); stV(buf ^ 1); }
        __syncthreads();
    }

    rs0 += __shfl_xor_sync(0xffffffffu, rs0, 1);
    rs0 += __shfl_xor_sync(0xffffffffu, rs0, 2);
    rs1 += __shfl_xor_sync(0xffffffffu, rs1, 1);
    rs1 += __shfl_xor_sync(0xffffffffu, rs1, 2);
    float i0 = 1.f / rs0, i1 = 1.f / rs1;

    float* Og = attn + (size_t)b * MM * HH + (size_t)(qt * 128) * HH + h * 64;
    int r = wm + (lane >> 2);
#pragma unroll
    for (int j = 0; j < 8; j++) {
        int c = j * 8 + (lane & 3) * 2;
        *(float2*)(Og + (size_t)r * HH + c)       = make_float2(o[j][0] * i0, o[j][1] * i0);
        *(float2*)(Og + (size_t)(r + 8) * HH + c) = make_float2(o[j][2] * i1, o[j][3] * i1);
    }
}

// merged lnres + scatter: out[b,idx] = tok[b,idx] + gate * LN(tok[b,idx] + rel)
__global__ void k_lnscatter(const float* __restrict__ tok, float* __restrict__ out,
                            const float* __restrict__ lg, const float* __restrict__ lb) {
    __shared__ float red[4];
    int t = blockIdx.x, tid = threadIdx.x;
    int b = t >> 9;
    int lane = tid & 31, wid = tid >> 5;
    const float* r = g_rel + (size_t)t * HH;
    const float* s = tok + ((size_t)b * NN + g_idx[t]) * HH;
    float* d = out + ((size_t)b * NN + g_idx[t]) * HH;

    float t0 = s[tid],       t1 = s[tid + 128],
          t2 = s[tid + 256], t3 = s[tid + 384];
    float v0 = t0 + r[tid];
    float v1 = t1 + r[tid + 128];
    float v2 = t2 + r[tid + 256];
    float v3 = t3 + r[tid + 384];

    float su = v0 + v1 + v2 + v3;
    float q = v0 * v0 + v1 * v1 + v2 * v2 + v3 * v3;
#pragma unroll
    for (int o = 16; o; o >>= 1) {
        su += __shfl_down_sync(0xffffffffu, su, o);
        q  += __shfl_down_sync(0xffffffffu, q, o);
    }
    if (lane == 0) { red[wid] = su; }
    __syncthreads();
    if (tid == 0) red[0] = red[0] + red[1] + red[2] + red[3];
    __syncthreads();
    float Ssu = red[0];
    __syncthreads();
    if (lane == 0) red[wid] = q;
    __syncthreads();
    if (tid == 0) red[0] = red[0] + red[1] + red[2] + red[3];
    __syncthreads();
    float Sq = red[0];

    float mean = Ssu * (1.f / HH);
    float var = Sq * (1.f / HH) - mean * mean;
    float rstd = rsqrtf(var + LNEPS);
    float gp = g_gate[b];
    d[tid]       = t0 + gp * ((v0 - mean) * rstd * lg[tid]       + lb[tid]);
    d[tid + 128] = t1 + gp * ((v1 - mean) * rstd * lg[tid + 128] + lb[tid + 128]);
    d[tid + 256] = t2 + gp * ((v2 - mean) * rstd * lg[tid + 256] + lb[tid + 256]);
    d[tid + 384] = t3 + gp * ((v3 - mean) * rstd * lg[tid + 384] + lb[tid + 384]);
}

// ---------------- launch ----------------
extern "C" void kernel_launch(void* const* d_in, const int* in_sizes, int n_in,
                              void* d_out, int out_size) {
    const float* tok        = (const float*)d_in[0];
    const float* gate_ln_g  = (const float*)d_in[1];
    const float* gate_ln_b  = (const float*)d_in[2];
    const float* gate_w     = (const float*)d_in[3];
    const float* gate_b     = (const float*)d_in[4];
    const float* sal_ln_g   = (const float*)d_in[5];
    const float* sal_ln_b   = (const float*)d_in[6];
    const float* sal_w      = (const float*)d_in[7];
    const float* sal_b      = (const float*)d_in[8];
    const float* in_proj_w  = (const float*)d_in[9];
    const float* in_proj_b  = (const float*)d_in[10];
    const float* out_proj_w = (const float*)d_in[11];
    const float* out_proj_b = (const float*)d_in[12];
    const float* rel_ln_g   = (const float*)d_in[13];
    const float* rel_ln_b   = (const float*)d_in[14];
    float* out = (float*)d_out;

    void *p_qkv_v, *p_attn_v, *p_rel_v;
    cudaGetSymbolAddress(&p_qkv_v, g_qkv);
    cudaGetSymbolAddress(&p_attn_v, g_attn);
    cudaGetSymbolAddress(&p_rel_v, g_rel);
    float* p_qkv = (float*)p_qkv_v;
    float* p_attn = (float*)p_attn_v;
    float* p_rel = (float*)p_rel_v;

    // one side stream + events, created ONCE (before the pre-capture baseline)
    static cudaStream_t s2 = nullptr;
    static cudaEvent_t eFork = nullptr, eCopy = nullptr;
    if (!s2) {
        cudaStreamCreateWithFlags(&s2, cudaStreamNonBlocking);
        cudaEventCreateWithFlags(&eFork, cudaEventDisableTiming);
        cudaEventCreateWithFlags(&eCopy, cudaEventDisableTiming);
    }

    cudaEventRecord(eFork, 0);
    cudaStreamWaitEvent(s2, eFork, 0);
    k_copy<<<64, 256, 0, s2>>>((const float4*)tok, (float4*)out);
    cudaEventRecord(eCopy, s2);

    k_poolsal<<<dim3(BB, 32), 512>>>(tok, sal_ln_g, sal_ln_b, sal_w, sal_b);
    k_pool2gate<<<BB, 512>>>(gate_ln_g, gate_ln_b, gate_w, gate_b);
    k_topk<<<BB, 512>>>();

    // qkv = gather(tok)[sel] @ in_proj_w^T + in_proj_b : M=8192, N=1536, K=512
    k_gemm_bf<128, 128, 2, 4, 1><<<dim3(12, 64, 1), 256>>>(
        tok, in_proj_w, in_proj_b, p_qkv, HH, HH, HH, 3 * HH, 1.f);

    // flash attention (S in registers)
    k_attn<<<BB * NHEAD * 4, 256>>>(p_qkv, p_attn);

    // rel = attn_out @ out_proj_w^T + out_proj_b : M=8192, N=512, K=512
    k_gemm_bf<128, 128, 2, 4, 0><<<dim3(4, 64, 1), 256>>>(
        p_attn, out_proj_w, out_proj_b, p_rel, HH, HH, HH, HH, 1.f);

    // join: lnscatter needs the copy done
    cudaStreamWaitEvent(0, eCopy, 0);
    k_lnscatter<<<BB * MM, 128>>>(tok, out, rel_ln_g, rel_ln_b);
}